// round 11
// baseline (speedup 1.0000x reference)
#include <cuda_runtime.h>
#include <cuda_fp16.h>
#include <cstdint>
#include <cstddef>

#define TT 8192
#define D  2048
#define NE 8
#define LR 16
#define MP 16640          // 16384 pairs + 8*32 segment padding
#define ALPHA 2.0f
#define N13 4352          // 2*D + 256 (Wup,Wgate,B1,B3 concatenated)

// ---------------- scratch (device globals; allocation-free) ----------------
__device__ __align__(256) __half g_Xh   [(size_t)TT * D];
__device__ __align__(256) __half g_W13B [(size_t)N13 * D];
__device__ __align__(256) __half g_Wdh  [(size_t)D * D];
__device__ __align__(256) __half g_B2h  [(size_t)128 * D];
__device__ __align__(256) __half g_Hph  [(size_t)MP * D];
__device__ __align__(256) __half g_Hc   [(size_t)TT * D];
__device__ __align__(256) __half g_H13h [(size_t)TT * N13];
__device__ __align__(256) float  g_U2   [(size_t)MP * 128];
__device__ int   g_sel[TT * 2];
__device__ float g_wtk[TT * 2];
__device__ int   g_cnt[NE];
__device__ int   g_off[NE + 1];
__device__ int   g_cur[NE];
__device__ int   g_pairTok[MP];
__device__ int   g_pairPos[TT * 2];

// ---------------- fp32 -> fp16 (rn) -----------------------------------------
__global__ void to_half_kernel(const float4* __restrict__ src,
                               __half2* __restrict__ dst, int n4)
{
    int i = blockIdx.x * 256 + threadIdx.x;
    if (i < n4) {
        float4 v = src[i];
        dst[2 * i]     = __floats2half2_rn(v.x, v.y);
        dst[2 * i + 1] = __floats2half2_rn(v.z, v.w);
    }
}

__global__ void reset_kernel()
{
    int i = blockIdx.x * 256 + threadIdx.x;
    if (i < NE) g_cnt[i] = 0;
    if (i < MP) g_pairTok[i] = -1;
}

// ---------------- router: logits (fp64 accum), top-2, softmax ---------------
__global__ void router_kernel(const float* __restrict__ X,
                              const float* __restrict__ Wg)
{
    int t = (blockIdx.x * blockDim.x + threadIdx.x) >> 5;
    int lane = threadIdx.x & 31;
    if (t >= TT) return;
    const float4* x4 = (const float4*)(X + (size_t)t * D);
    double acc[NE];
#pragma unroll
    for (int e = 0; e < NE; e++) acc[e] = 0.0;
    for (int it = 0; it < 16; it++) {
        float4 xv = x4[it * 32 + lane];
#pragma unroll
        for (int e = 0; e < NE; e++) {
            float4 wv = ((const float4*)(Wg + (size_t)e * D))[it * 32 + lane];
            acc[e] += (double)xv.x * wv.x + (double)xv.y * wv.y
                    + (double)xv.z * wv.z + (double)xv.w * wv.w;
        }
    }
#pragma unroll
    for (int e = 0; e < NE; e++)
#pragma unroll
        for (int o = 16; o > 0; o >>= 1)
            acc[e] += __shfl_xor_sync(0xffffffffu, acc[e], o);
    if (lane == 0) {
        int e0 = 0; double b0 = acc[0];
#pragma unroll
        for (int e = 1; e < NE; e++) if (acc[e] > b0) { b0 = acc[e]; e0 = e; }
        int e1 = -1; double b1 = -1e300;
#pragma unroll
        for (int e = 0; e < NE; e++)
            if (e != e0 && acc[e] > b1) { b1 = acc[e]; e1 = e; }
        float ew = expf((float)(b1 - b0));
        float w0 = 1.f / (1.f + ew);
        float w1 = ew * w0;
        g_sel[t * 2] = e0; g_sel[t * 2 + 1] = e1;
        g_wtk[t * 2] = w0; g_wtk[t * 2 + 1] = w1;
        atomicAdd(&g_cnt[e0], 1);
        atomicAdd(&g_cnt[e1], 1);
    }
}

__global__ void scan_kernel()
{
    int o = 0;
    for (int e = 0; e < NE; e++) {
        g_off[e] = o; g_cur[e] = o;
        o += (g_cnt[e] + 31) & ~31;
    }
    g_off[NE] = o;
}

__global__ void assign_kernel()
{
    int i = blockIdx.x * 256 + threadIdx.x;
    if (i < TT * 2) {
        int e = g_sel[i];
        int p = atomicAdd(&g_cur[e], 1);
        g_pairTok[p] = i >> 1;
        g_pairPos[i] = p;
    }
}

__device__ __forceinline__ uint32_t swz(uint32_t off) {
    return off ^ ((off >> 3) & 0x70u);
}

// ---------------- fp16 GEMM 128x256x64: C[M,N] = A[M,K] @ B[N,K]^T ----------
// 8 warps (2m x 4n, warp tile 64x64), 3-stage cp.async, SW128 smem, ldmatrix.
#define STG2_BY 49152             // (128 + 256) rows * 128B
#define A2_BY   16384

template<typename OutT>
__global__ void __launch_bounds__(256, 1) gemm256(const __half* __restrict__ A,
                                                  const __half* __restrict__ B,
                                                  OutT* __restrict__ C,
                                                  int Nld, int K)
{
    extern __shared__ char smem[];
    const int tid = threadIdx.x, lane = tid & 31, wid = tid >> 5;
    const int wm = wid & 1, wn = wid >> 1;
    uint32_t sb;
    asm("{ .reg .u64 t; cvta.to.shared.u64 t, %1; cvt.u32.u64 %0, t; }"
        : "=r"(sb) : "l"(smem));

    const __half* Ab = A + (size_t)blockIdx.y * 128 * K;
    const __half* Bb = B + (size_t)blockIdx.x * 256 * K;
    const int KT = K >> 6;

    auto load_tile = [&](int kt, int st) {
        uint32_t base = sb + st * STG2_BY;
#pragma unroll
        for (int i = 0; i < 12; i++) {
            int f = tid + i * 256;          // 3072 chunks of 16B; 8 per row
            const __half* src;
            uint32_t off;
            if (f < 1024) {                 // A: 128 rows x 8 chunks
                int r = f >> 3, q = f & 7;
                src = Ab + (size_t)r * K + kt * 64 + q * 8;
                off = swz((uint32_t)(r * 128 + q * 16));
            } else {                        // B: 256 rows x 8 chunks
                int f2 = f - 1024;
                int r = f2 >> 3, q = f2 & 7;
                src = Bb + (size_t)r * K + kt * 64 + q * 8;
                off = A2_BY + swz((uint32_t)(r * 128 + q * 16));
            }
            asm volatile("cp.async.cg.shared.global [%0], [%1], 16;"
                         :: "r"(base + off), "l"(src));
        }
        asm volatile("cp.async.commit_group;");
    };

    float acc[4][8][4];
#pragma unroll
    for (int i = 0; i < 4; i++)
#pragma unroll
        for (int j = 0; j < 8; j++)
#pragma unroll
            for (int k = 0; k < 4; k++) acc[i][j][k] = 0.f;

    load_tile(0, 0);
    load_tile(1, 1);

    const int lrow = lane & 15, lcol = (lane >> 4) << 4;

#pragma unroll 1
    for (int kt = 0; kt < KT; kt++) {
        if (kt + 1 < KT) asm volatile("cp.async.wait_group 1;");
        else             asm volatile("cp.async.wait_group 0;");
        __syncthreads();
        if (kt + 2 < KT) load_tile(kt + 2, (kt + 2) % 3);

        uint32_t sA = sb + (kt % 3) * STG2_BY;
        uint32_t sB = sA + A2_BY;
#pragma unroll
        for (int kk = 0; kk < 4; kk++) {
            uint32_t af[4][4], bf[8][2];
#pragma unroll
            for (int mi = 0; mi < 4; mi++) {
                int row = wm * 64 + mi * 16 + lrow;
                uint32_t ad = sA + swz((uint32_t)(row * 128 + kk * 32 + lcol));
                asm volatile(
                    "ldmatrix.sync.aligned.m8n8.x4.shared.b16 {%0,%1,%2,%3}, [%4];"
                    : "=r"(af[mi][0]), "=r"(af[mi][1]),
                      "=r"(af[mi][2]), "=r"(af[mi][3]) : "r"(ad));
            }
#pragma unroll
            for (int bi = 0; bi < 4; bi++) {
                int row = wn * 64 + bi * 16 + lrow;
                uint32_t bd = sB + swz((uint32_t)(row * 128 + kk * 32 + lcol));
                uint32_t r0, r1, r2, r3;
                asm volatile(
                    "ldmatrix.sync.aligned.m8n8.x4.shared.b16 {%0,%1,%2,%3}, [%4];"
                    : "=r"(r0), "=r"(r1), "=r"(r2), "=r"(r3) : "r"(bd));
                bf[2 * bi][0] = r0;     bf[2 * bi][1] = r2;
                bf[2 * bi + 1][0] = r1; bf[2 * bi + 1][1] = r3;
            }
#pragma unroll
            for (int mi = 0; mi < 4; mi++)
#pragma unroll
                for (int ni = 0; ni < 8; ni++)
                    asm volatile(
                        "mma.sync.aligned.m16n8k16.row.col.f32.f16.f16.f32 "
                        "{%0,%1,%2,%3}, {%4,%5,%6,%7}, {%8,%9}, {%0,%1,%2,%3};"
                        : "+f"(acc[mi][ni][0]), "+f"(acc[mi][ni][1]),
                          "+f"(acc[mi][ni][2]), "+f"(acc[mi][ni][3])
                        : "r"(af[mi][0]), "r"(af[mi][1]),
                          "r"(af[mi][2]), "r"(af[mi][3]),
                          "r"(bf[ni][0]), "r"(bf[ni][1]));
        }
        __syncthreads();
    }

    const int g = lane >> 2, c = lane & 3;
    int mBase = blockIdx.y * 128 + wm * 64;
    int nBase = blockIdx.x * 256 + wn * 64;
#pragma unroll
    for (int mi = 0; mi < 4; mi++)
#pragma unroll
        for (int ni = 0; ni < 8; ni++) {
            int row0 = mBase + mi * 16 + g;
            int col  = nBase + ni * 8 + c * 2;
            if constexpr (sizeof(OutT) == 2) {
                *(__half2*)&C[(size_t)row0 * Nld + col] =
                    __floats2half2_rn(acc[mi][ni][0], acc[mi][ni][1]);
                *(__half2*)&C[(size_t)(row0 + 8) * Nld + col] =
                    __floats2half2_rn(acc[mi][ni][2], acc[mi][ni][3]);
            } else {
                *(float2*)&C[(size_t)row0 * Nld + col] =
                    make_float2(acc[mi][ni][0], acc[mi][ni][1]);
                *(float2*)&C[(size_t)(row0 + 8) * Nld + col] =
                    make_float2(acc[mi][ni][2], acc[mi][ni][3]);
            }
        }
}

// ---------------- fp16 GEMM 128x128x64 (for skinny U2) ----------------------
#define STAGE_BY 32768
#define A_BY     16384

__global__ void __launch_bounds__(256, 2) gemm_h16(const __half* __restrict__ A,
                                                   const __half* __restrict__ B,
                                                   float* __restrict__ C,
                                                   int Nld, int K)
{
    extern __shared__ char smem[];
    const int tid = threadIdx.x, lane = tid & 31, wid = tid >> 5;
    const int wm = wid & 1, wn = wid >> 1;
    uint32_t sb;
    asm("{ .reg .u64 t; cvta.to.shared.u64 t, %1; cvt.u32.u64 %0, t; }"
        : "=r"(sb) : "l"(smem));

    const __half* Ab = A + (size_t)blockIdx.y * 128 * K;
    const __half* Bb = B + (size_t)blockIdx.x * 128 * K;
    const int KT = K >> 6;

    auto load_tile = [&](int kt, int st) {
        uint32_t base = sb + st * STAGE_BY;
#pragma unroll
        for (int i = 0; i < 8; i++) {
            int f = tid + i * 256;
            const __half* src;
            uint32_t off;
            if (f < 1024) {
                int r = f >> 3, q = f & 7;
                src = Ab + (size_t)r * K + kt * 64 + q * 8;
                off = swz((uint32_t)(r * 128 + q * 16));
            } else {
                int f2 = f - 1024;
                int r = f2 >> 3, q = f2 & 7;
                src = Bb + (size_t)r * K + kt * 64 + q * 8;
                off = A_BY + swz((uint32_t)(r * 128 + q * 16));
            }
            asm volatile("cp.async.cg.shared.global [%0], [%1], 16;"
                         :: "r"(base + off), "l"(src));
        }
        asm volatile("cp.async.commit_group;");
    };

    float acc[4][4][4];
#pragma unroll
    for (int i = 0; i < 4; i++)
#pragma unroll
        for (int j = 0; j < 4; j++)
#pragma unroll
            for (int k = 0; k < 4; k++) acc[i][j][k] = 0.f;

    load_tile(0, 0);
    load_tile(1, 1);

    const int lrow = lane & 15, lcol = (lane >> 4) << 4;

#pragma unroll 1
    for (int kt = 0; kt < KT; kt++) {
        if (kt + 1 < KT) asm volatile("cp.async.wait_group 1;");
        else             asm volatile("cp.async.wait_group 0;");
        __syncthreads();
        if (kt + 2 < KT) load_tile(kt + 2, (kt + 2) % 3);

        uint32_t sA = sb + (kt % 3) * STAGE_BY;
        uint32_t sB = sA + A_BY;
#pragma unroll
        for (int kk = 0; kk < 4; kk++) {
            uint32_t af[4][4], bf[4][2];
#pragma unroll
            for (int mi = 0; mi < 4; mi++) {
                int row = wm * 64 + mi * 16 + lrow;
                uint32_t ad = sA + swz((uint32_t)(row * 128 + kk * 32 + lcol));
                asm volatile(
                    "ldmatrix.sync.aligned.m8n8.x4.shared.b16 {%0,%1,%2,%3}, [%4];"
                    : "=r"(af[mi][0]), "=r"(af[mi][1]),
                      "=r"(af[mi][2]), "=r"(af[mi][3]) : "r"(ad));
            }
#pragma unroll
            for (int bi = 0; bi < 2; bi++) {
                int row = wn * 32 + bi * 16 + lrow;
                uint32_t bd = sB + swz((uint32_t)(row * 128 + kk * 32 + lcol));
                uint32_t r0, r1, r2, r3;
                asm volatile(
                    "ldmatrix.sync.aligned.m8n8.x4.shared.b16 {%0,%1,%2,%3}, [%4];"
                    : "=r"(r0), "=r"(r1), "=r"(r2), "=r"(r3) : "r"(bd));
                bf[2 * bi][0] = r0;     bf[2 * bi][1] = r2;
                bf[2 * bi + 1][0] = r1; bf[2 * bi + 1][1] = r3;
            }
#pragma unroll
            for (int mi = 0; mi < 4; mi++)
#pragma unroll
                for (int ni = 0; ni < 4; ni++)
                    asm volatile(
                        "mma.sync.aligned.m16n8k16.row.col.f32.f16.f16.f32 "
                        "{%0,%1,%2,%3}, {%4,%5,%6,%7}, {%8,%9}, {%0,%1,%2,%3};"
                        : "+f"(acc[mi][ni][0]), "+f"(acc[mi][ni][1]),
                          "+f"(acc[mi][ni][2]), "+f"(acc[mi][ni][3])
                        : "r"(af[mi][0]), "r"(af[mi][1]),
                          "r"(af[mi][2]), "r"(af[mi][3]),
                          "r"(bf[ni][0]), "r"(bf[ni][1]));
        }
        __syncthreads();
    }

    const int g = lane >> 2, c = lane & 3;
    int mBase = blockIdx.y * 128 + wm * 64;
    int nBase = blockIdx.x * 128 + wn * 32;
#pragma unroll
    for (int mi = 0; mi < 4; mi++)
#pragma unroll
        for (int ni = 0; ni < 4; ni++) {
            int row0 = mBase + mi * 16 + g;
            int col  = nBase + ni * 8 + c * 2;
            *(float2*)&C[(size_t)row0 * Nld + col]       = make_float2(acc[mi][ni][0], acc[mi][ni][1]);
            *(float2*)&C[(size_t)(row0 + 8) * Nld + col] = make_float2(acc[mi][ni][2], acc[mi][ni][3]);
        }
}

// ---------------- per-pair LoRA up deltas + SwiGLU (fp16 in/out) ------------
__global__ void __launch_bounds__(256) pair_up_kernel(const float* __restrict__ A1,
                                                      const float* __restrict__ A3)
{
    __shared__ float sA1[128 * 17], sA3[128 * 17];
    __shared__ float sU[32][33];
    __shared__ int   sTok[32];
    __shared__ int   sE;
    int p0 = blockIdx.x * 32, col0 = blockIdx.y * 128, tid = threadIdx.x;
    if (tid < 32) sTok[tid] = g_pairTok[p0 + tid];
    if (tid == 0) {
        int e = 0;
        while (e < NE - 1 && g_off[e + 1] <= p0) e++;
        sE = e;
    }
    __syncthreads();
    int e = sE;
    {
        int col = tid >> 1, half = tid & 1;
        const float* a1 = A1 + ((size_t)e * D + col0 + col) * LR + half * 8;
        const float* a3 = A3 + ((size_t)e * D + col0 + col) * LR + half * 8;
        float4 v0 = ((const float4*)a1)[0], v1 = ((const float4*)a1)[1];
        float* d1 = &sA1[col * 17 + half * 8];
        d1[0]=v0.x; d1[1]=v0.y; d1[2]=v0.z; d1[3]=v0.w;
        d1[4]=v1.x; d1[5]=v1.y; d1[6]=v1.z; d1[7]=v1.w;
        v0 = ((const float4*)a3)[0]; v1 = ((const float4*)a3)[1];
        float* d3 = &sA3[col * 17 + half * 8];
        d3[0]=v0.x; d3[1]=v0.y; d3[2]=v0.z; d3[3]=v0.w;
        d3[4]=v1.x; d3[5]=v1.y; d3[6]=v1.z; d3[7]=v1.w;
    }
    {   // per-pair LoRA-up values live in H13h columns [4096, 4352)
        int p = tid >> 3, j = tid & 7;
        int tok = sTok[p];
#pragma unroll
        for (int k = 0; k < 4; k++) {
            int v = j * 4 + k;
            float val = 0.f;
            if (tok >= 0) {
                int n = (v < 16) ? (4096 + e * LR + v) : (4096 + 128 + e * LR + (v - 16));
                val = __half2float(g_H13h[(size_t)tok * N13 + n]);
            }
            sU[p][v] = val;
        }
    }
    __syncthreads();
    for (int idx = tid; idx < 32 * 128; idx += 256) {
        int p = idx >> 7, col = idx & 127;
        int tok = sTok[p];
        float h1 = 0.f, h3 = 0.f;
        if (tok >= 0) {
            h1 = __half2float(g_H13h[(size_t)tok * N13 + col0 + col]);
            h3 = __half2float(g_H13h[(size_t)tok * N13 + D + col0 + col]);
        }
        float d1 = 0.f, d3 = 0.f;
#pragma unroll
        for (int r = 0; r < LR; r++) {
            d1 += sU[p][r]      * sA1[col * 17 + r];
            d3 += sU[p][16 + r] * sA3[col * 17 + r];
        }
        h1 += ALPHA * d1;
        h3 += ALPHA * d3;
        float s = h1 / (1.f + expf(-h1));
        g_Hph[(size_t)(p0 + p) * D + col0 + col] = __float2half_rn(s * h3);
    }
}

// ---------------- weighted 2-way combine of Hp rows (fp16 out) --------------
__global__ void combine_kernel()
{
    int i = blockIdx.x * 256 + threadIdx.x;   // over TT * (D/8)
    if (i >= TT * (D / 8)) return;
    int t = i >> 8;                            // D/8 = 256
    int c8 = i & 255;
    int pos0 = g_pairPos[t * 2], pos1 = g_pairPos[t * 2 + 1];
    float w0 = g_wtk[t * 2], w1 = g_wtk[t * 2 + 1];
    const __half2* a = (const __half2*)(g_Hph + (size_t)pos0 * D) + c8 * 4;
    const __half2* b = (const __half2*)(g_Hph + (size_t)pos1 * D) + c8 * 4;
    __half2* o = (__half2*)(g_Hc + (size_t)t * D) + c8 * 4;
#pragma unroll
    for (int j = 0; j < 4; j++) {
        float2 av = __half22float2(a[j]);
        float2 bv = __half22float2(b[j]);
        o[j] = __floats2half2_rn(w0 * av.x + w1 * bv.x, w0 * av.y + w1 * bv.y);
    }
}

// ---------------- final: out += ALPHA * sum_k w_k * U2[pos_k] @ A2[e_k]^T ---
__global__ void __launch_bounds__(256) final_delta_kernel(const float* __restrict__ A2,
                                                          float* __restrict__ out)
{
    extern __shared__ float sA2[];        // [e][r][col] = e*2048 + r*128 + col
    __shared__ float sU[64][32];
    __shared__ int   sEl[64][2];
    int col0 = blockIdx.x * 128, t0 = blockIdx.y * 64, tid = threadIdx.x;

#pragma unroll
    for (int it = 0; it < 4; it++) {
        int pc = tid + it * 256;          // (e, col)
        int e = pc >> 7, col = pc & 127;
        const float4* src = (const float4*)(A2 + ((size_t)e * D + col0 + col) * LR);
#pragma unroll
        for (int j = 0; j < 4; j++) {
            float4 v = src[j];
            float* dst = &sA2[e * 2048 + (j * 4) * 128 + col];
            dst[0]   = v.x; dst[128] = v.y; dst[256] = v.z; dst[384] = v.w;
        }
    }
#pragma unroll
    for (int it = 0; it < 8; it++) {
        int idx = tid + it * 256;         // 2048
        int tok = idx >> 5, v = idx & 31;
        int k = v >> 4, r = v & 15;
        int gi = (t0 + tok) * 2 + k;
        int pos = g_pairPos[gi];
        int e   = g_sel[gi];
        sU[tok][v] = g_wtk[gi] * g_U2[(size_t)pos * 128 + e * LR + r];
        if (r == 0) sEl[tok][k] = e;
    }
    __syncthreads();

#pragma unroll 4
    for (int it = 0; it < 32; it++) {
        int idx = tid + it * 256;         // 64*128
        int tok = idx >> 7, col = idx & 127;
        float d = 0.f;
#pragma unroll
        for (int k = 0; k < 2; k++) {
            const float* a2c = &sA2[sEl[tok][k] * 2048 + col];
            const float* u = &sU[tok][k * 16];
#pragma unroll
            for (int r = 0; r < LR; r++) d += u[r] * a2c[r * 128];
        }
        size_t oidx = (size_t)(t0 + tok) * D + col0 + col;
        out[oidx] += ALPHA * d;
    }
}

// ---------------- launch ----------------------------------------------------
extern "C" void kernel_launch(void* const* d_in, const int* in_sizes, int n_in,
                              void* d_out, int out_size)
{
    const float* X     = (const float*)d_in[0];
    const float* Wg    = (const float*)d_in[1];
    const float* Wup   = (const float*)d_in[2];
    const float* Wgate = (const float*)d_in[3];
    const float* Wdown = (const float*)d_in[4];
    const float* A1    = (const float*)d_in[5];
    const float* B1    = (const float*)d_in[6];
    const float* A2    = (const float*)d_in[7];
    const float* B2    = (const float*)d_in[8];
    const float* A3    = (const float*)d_in[9];
    const float* B3    = (const float*)d_in[10];
    float* out = (float*)d_out;

    static __half *pXh = nullptr, *pW13B, *pWdh, *pB2h, *pHph, *pHc, *pH13h;
    static float  *pU2;
    if (!pXh) {
        cudaGetSymbolAddress((void**)&pXh,   g_Xh);
        cudaGetSymbolAddress((void**)&pW13B, g_W13B);
        cudaGetSymbolAddress((void**)&pWdh,  g_Wdh);
        cudaGetSymbolAddress((void**)&pB2h,  g_B2h);
        cudaGetSymbolAddress((void**)&pHph,  g_Hph);
        cudaGetSymbolAddress((void**)&pHc,   g_Hc);
        cudaGetSymbolAddress((void**)&pH13h, g_H13h);
        cudaGetSymbolAddress((void**)&pU2,   g_U2);
        cudaFuncSetAttribute(gemm256<__half>,
            cudaFuncAttributeMaxDynamicSharedMemorySize, 3 * STG2_BY);
        cudaFuncSetAttribute(gemm256<float>,
            cudaFuncAttributeMaxDynamicSharedMemorySize, 3 * STG2_BY);
        cudaFuncSetAttribute(gemm_h16,
            cudaFuncAttributeMaxDynamicSharedMemorySize, 3 * STAGE_BY);
        cudaFuncSetAttribute(final_delta_kernel,
            cudaFuncAttributeMaxDynamicSharedMemorySize, 65536);
    }
    const int SMB2 = 3 * STG2_BY;   // 147456
    const int SMB  = 3 * STAGE_BY;  //  98304

    reset_kernel<<<(MP + 255) / 256, 256>>>();

    auto cvt = [&](const float* s, __half* d, size_t n) {
        int n4 = (int)(n / 4);
        to_half_kernel<<<(n4 + 255) / 256, 256>>>((const float4*)s, (__half2*)d, n4);
    };
    cvt(X,     pXh,                      (size_t)TT * D);
    cvt(Wup,   pW13B,                    (size_t)D * D);
    cvt(Wgate, pW13B + (size_t)D * D,    (size_t)D * D);
    cvt(B1,    pW13B + (size_t)2 * D * D,(size_t)128 * D);
    cvt(B3,    pW13B + (size_t)2 * D * D + (size_t)128 * D, (size_t)128 * D);
    cvt(Wdown, pWdh,                     (size_t)D * D);
    cvt(B2,    pB2h,                     (size_t)128 * D);

    router_kernel<<<TT * 32 / 256, 256>>>(X, Wg);
    scan_kernel<<<1, 1>>>();
    assign_kernel<<<(TT * 2 + 255) / 256, 256>>>();

    // H13h = Xh @ [Wup;Wgate;B1;B3]^T    [8192 x 4352] fp16
    gemm256<__half><<<dim3(N13 / 256, TT / 128), 256, SMB2>>>(pXh, pW13B, pH13h, N13, D);

    pair_up_kernel<<<dim3(MP / 32, D / 128), 256>>>(A1, A3);

    combine_kernel<<<TT * (D / 8) / 256, 256>>>();

    // U2 = Hph @ B2^T                    [16640 x 128]
    gemm_h16<<<dim3(1, MP / 128), 256, SMB>>>(pHph, pB2h, pU2, 128, D);

    // out_base = Hc @ Wdown^T            [8192 x 2048]  (writes d_out directly)
    gemm256<float><<<dim3(D / 256, TT / 128), 256, SMB2>>>(pHc, pWdh, out, D, D);

    final_delta_kernel<<<dim3(D / 128, TT / 64), 256, 65536>>>(A2, out);
    (void)in_sizes; (void)n_in; (void)out_size;
}

// round 13
// speedup vs baseline: 1.0686x; 1.0686x over previous
#include <cuda_runtime.h>
#include <cuda_fp16.h>
#include <cstdint>
#include <cstddef>

#define TT 8192
#define D  2048
#define NE 8
#define LR 16
#define MP 16640          // 16384 pairs + 8*32 segment padding
#define ALPHA 2.0f
#define N13 4352          // 2*D + 256 (Wup,Wgate,B1,B3 concatenated)

// ---------------- scratch (device globals; allocation-free) ----------------
__device__ __align__(256) __half g_Xh   [(size_t)TT * D];
__device__ __align__(256) __half g_W13B [(size_t)N13 * D];
__device__ __align__(256) __half g_Wdh  [(size_t)D * D];
__device__ __align__(256) __half g_B2h  [(size_t)128 * D];
__device__ __align__(256) __half g_Hph  [(size_t)MP * D];
__device__ __align__(256) __half g_Hc   [(size_t)TT * D];
__device__ __align__(256) __half g_H13h [(size_t)TT * N13];
__device__ __align__(256) float  g_U2   [(size_t)MP * 128];
__device__ int   g_sel[TT * 2];
__device__ float g_wtk[TT * 2];
__device__ int   g_cnt[NE];
__device__ int   g_off[NE + 1];
__device__ int   g_cur[NE];
__device__ int   g_pairTok[MP];
__device__ int   g_pairPos[TT * 2];

// ---------------- fp32 -> fp16 (rn) -----------------------------------------
__global__ void to_half_kernel(const float4* __restrict__ src,
                               __half2* __restrict__ dst, int n4)
{
    int i = blockIdx.x * 256 + threadIdx.x;
    if (i < n4) {
        float4 v = src[i];
        dst[2 * i]     = __floats2half2_rn(v.x, v.y);
        dst[2 * i + 1] = __floats2half2_rn(v.z, v.w);
    }
}

__global__ void reset_kernel()
{
    int i = blockIdx.x * 256 + threadIdx.x;
    if (i < NE) g_cnt[i] = 0;
    if (i < MP) g_pairTok[i] = -1;
}

// ---------------- router: logits (fp64 accum), top-2, softmax ---------------
__global__ void router_kernel(const float* __restrict__ X,
                              const float* __restrict__ Wg)
{
    int t = (blockIdx.x * blockDim.x + threadIdx.x) >> 5;
    int lane = threadIdx.x & 31;
    if (t >= TT) return;
    const float4* x4 = (const float4*)(X + (size_t)t * D);
    double acc[NE];
#pragma unroll
    for (int e = 0; e < NE; e++) acc[e] = 0.0;
    for (int it = 0; it < 16; it++) {
        float4 xv = x4[it * 32 + lane];
#pragma unroll
        for (int e = 0; e < NE; e++) {
            float4 wv = ((const float4*)(Wg + (size_t)e * D))[it * 32 + lane];
            acc[e] += (double)xv.x * wv.x + (double)xv.y * wv.y
                    + (double)xv.z * wv.z + (double)xv.w * wv.w;
        }
    }
#pragma unroll
    for (int e = 0; e < NE; e++)
#pragma unroll
        for (int o = 16; o > 0; o >>= 1)
            acc[e] += __shfl_xor_sync(0xffffffffu, acc[e], o);
    if (lane == 0) {
        int e0 = 0; double b0 = acc[0];
#pragma unroll
        for (int e = 1; e < NE; e++) if (acc[e] > b0) { b0 = acc[e]; e0 = e; }
        int e1 = -1; double b1 = -1e300;
#pragma unroll
        for (int e = 0; e < NE; e++)
            if (e != e0 && acc[e] > b1) { b1 = acc[e]; e1 = e; }
        float ew = expf((float)(b1 - b0));
        float w0 = 1.f / (1.f + ew);
        float w1 = ew * w0;
        g_sel[t * 2] = e0; g_sel[t * 2 + 1] = e1;
        g_wtk[t * 2] = w0; g_wtk[t * 2 + 1] = w1;
        atomicAdd(&g_cnt[e0], 1);
        atomicAdd(&g_cnt[e1], 1);
    }
}

__global__ void scan_kernel()
{
    int o = 0;
    for (int e = 0; e < NE; e++) {
        g_off[e] = o; g_cur[e] = o;
        o += (g_cnt[e] + 31) & ~31;
    }
    g_off[NE] = o;
}

__global__ void assign_kernel()
{
    int i = blockIdx.x * 256 + threadIdx.x;
    if (i < TT * 2) {
        int e = g_sel[i];
        int p = atomicAdd(&g_cur[e], 1);
        g_pairTok[p] = i >> 1;
        g_pairPos[i] = p;
    }
}

__device__ __forceinline__ uint32_t swz(uint32_t off) {
    return off ^ ((off >> 3) & 0x70u);
}

// ---------------- fp16 GEMM 128x128x64: C[M,N] = A[M,K] @ B[N,K]^T ----------
// 8 warps (2m x 4n, warp tile 64x32), 3-stage cp.async, SW128 smem, ldmatrix,
// 2 CTAs/SM. Proven R8 mainloop; output type templated (fp16 or fp32).
#define STAGE_BY 32768
#define A_BY     16384

template<typename OutT>
__global__ void __launch_bounds__(256, 2) gemm_h16(const __half* __restrict__ A,
                                                   const __half* __restrict__ B,
                                                   OutT* __restrict__ C,
                                                   int Nld, int K)
{
    extern __shared__ char smem[];
    const int tid = threadIdx.x, lane = tid & 31, wid = tid >> 5;
    const int wm = wid & 1, wn = wid >> 1;
    uint32_t sb;
    asm("{ .reg .u64 t; cvta.to.shared.u64 t, %1; cvt.u32.u64 %0, t; }"
        : "=r"(sb) : "l"(smem));

    const __half* Ab = A + (size_t)blockIdx.y * 128 * K;
    const __half* Bb = B + (size_t)blockIdx.x * 128 * K;
    const int KT = K >> 6;

    auto load_tile = [&](int kt, int st) {
        uint32_t base = sb + st * STAGE_BY;
#pragma unroll
        for (int i = 0; i < 8; i++) {
            int f = tid + i * 256;          // 2048 chunks of 16B; 8 per row
            const __half* src;
            uint32_t off;
            if (f < 1024) {
                int r = f >> 3, q = f & 7;
                src = Ab + (size_t)r * K + kt * 64 + q * 8;
                off = swz((uint32_t)(r * 128 + q * 16));
            } else {
                int f2 = f - 1024;
                int r = f2 >> 3, q = f2 & 7;
                src = Bb + (size_t)r * K + kt * 64 + q * 8;
                off = A_BY + swz((uint32_t)(r * 128 + q * 16));
            }
            asm volatile("cp.async.cg.shared.global [%0], [%1], 16;"
                         :: "r"(base + off), "l"(src));
        }
        asm volatile("cp.async.commit_group;");
    };

    float acc[4][4][4];
#pragma unroll
    for (int i = 0; i < 4; i++)
#pragma unroll
        for (int j = 0; j < 4; j++)
#pragma unroll
            for (int k = 0; k < 4; k++) acc[i][j][k] = 0.f;

    load_tile(0, 0);
    load_tile(1, 1);

    const int lrow = lane & 15, lcol = (lane >> 4) << 4;

#pragma unroll 1
    for (int kt = 0; kt < KT; kt++) {
        if (kt + 1 < KT) asm volatile("cp.async.wait_group 1;");
        else             asm volatile("cp.async.wait_group 0;");
        __syncthreads();
        if (kt + 2 < KT) load_tile(kt + 2, (kt + 2) % 3);

        uint32_t sA = sb + (kt % 3) * STAGE_BY;
        uint32_t sB = sA + A_BY;
#pragma unroll
        for (int kk = 0; kk < 4; kk++) {
            uint32_t af[4][4], bf[4][2];
#pragma unroll
            for (int mi = 0; mi < 4; mi++) {
                int row = wm * 64 + mi * 16 + lrow;
                uint32_t ad = sA + swz((uint32_t)(row * 128 + kk * 32 + lcol));
                asm volatile(
                    "ldmatrix.sync.aligned.m8n8.x4.shared.b16 {%0,%1,%2,%3}, [%4];"
                    : "=r"(af[mi][0]), "=r"(af[mi][1]),
                      "=r"(af[mi][2]), "=r"(af[mi][3]) : "r"(ad));
            }
#pragma unroll
            for (int bi = 0; bi < 2; bi++) {
                int row = wn * 32 + bi * 16 + lrow;
                uint32_t bd = sB + swz((uint32_t)(row * 128 + kk * 32 + lcol));
                uint32_t r0, r1, r2, r3;
                asm volatile(
                    "ldmatrix.sync.aligned.m8n8.x4.shared.b16 {%0,%1,%2,%3}, [%4];"
                    : "=r"(r0), "=r"(r1), "=r"(r2), "=r"(r3) : "r"(bd));
                bf[2 * bi][0] = r0;     bf[2 * bi][1] = r2;
                bf[2 * bi + 1][0] = r1; bf[2 * bi + 1][1] = r3;
            }
#pragma unroll
            for (int mi = 0; mi < 4; mi++)
#pragma unroll
                for (int ni = 0; ni < 4; ni++)
                    asm volatile(
                        "mma.sync.aligned.m16n8k16.row.col.f32.f16.f16.f32 "
                        "{%0,%1,%2,%3}, {%4,%5,%6,%7}, {%8,%9}, {%0,%1,%2,%3};"
                        : "+f"(acc[mi][ni][0]), "+f"(acc[mi][ni][1]),
                          "+f"(acc[mi][ni][2]), "+f"(acc[mi][ni][3])
                        : "r"(af[mi][0]), "r"(af[mi][1]),
                          "r"(af[mi][2]), "r"(af[mi][3]),
                          "r"(bf[ni][0]), "r"(bf[ni][1]));
        }
        __syncthreads();
    }

    const int g = lane >> 2, c = lane & 3;
    int mBase = blockIdx.y * 128 + wm * 64;
    int nBase = blockIdx.x * 128 + wn * 32;
#pragma unroll
    for (int mi = 0; mi < 4; mi++)
#pragma unroll
        for (int ni = 0; ni < 4; ni++) {
            int row0 = mBase + mi * 16 + g;
            int col  = nBase + ni * 8 + c * 2;
            if constexpr (sizeof(OutT) == 2) {
                *(__half2*)&C[(size_t)row0 * Nld + col] =
                    __floats2half2_rn(acc[mi][ni][0], acc[mi][ni][1]);
                *(__half2*)&C[(size_t)(row0 + 8) * Nld + col] =
                    __floats2half2_rn(acc[mi][ni][2], acc[mi][ni][3]);
            } else {
                *(float2*)&C[(size_t)row0 * Nld + col] =
                    make_float2(acc[mi][ni][0], acc[mi][ni][1]);
                *(float2*)&C[(size_t)(row0 + 8) * Nld + col] =
                    make_float2(acc[mi][ni][2], acc[mi][ni][3]);
            }
        }
}

// ---------------- per-pair LoRA up deltas + SwiGLU (fp16 in/out) ------------
__global__ void __launch_bounds__(256) pair_up_kernel(const float* __restrict__ A1,
                                                      const float* __restrict__ A3)
{
    __shared__ float sA1[128 * 17], sA3[128 * 17];
    __shared__ float sU[32][33];
    __shared__ int   sTok[32];
    __shared__ int   sE;
    int p0 = blockIdx.x * 32, col0 = blockIdx.y * 128, tid = threadIdx.x;
    if (tid < 32) sTok[tid] = g_pairTok[p0 + tid];
    if (tid == 0) {
        int e = 0;
        while (e < NE - 1 && g_off[e + 1] <= p0) e++;
        sE = e;
    }
    __syncthreads();
    int e = sE;
    {
        int col = tid >> 1, half = tid & 1;
        const float* a1 = A1 + ((size_t)e * D + col0 + col) * LR + half * 8;
        const float* a3 = A3 + ((size_t)e * D + col0 + col) * LR + half * 8;
        float4 v0 = ((const float4*)a1)[0], v1 = ((const float4*)a1)[1];
        float* d1 = &sA1[col * 17 + half * 8];
        d1[0]=v0.x; d1[1]=v0.y; d1[2]=v0.z; d1[3]=v0.w;
        d1[4]=v1.x; d1[5]=v1.y; d1[6]=v1.z; d1[7]=v1.w;
        v0 = ((const float4*)a3)[0]; v1 = ((const float4*)a3)[1];
        float* d3 = &sA3[col * 17 + half * 8];
        d3[0]=v0.x; d3[1]=v0.y; d3[2]=v0.z; d3[3]=v0.w;
        d3[4]=v1.x; d3[5]=v1.y; d3[6]=v1.z; d3[7]=v1.w;
    }
    {   // per-pair LoRA-up values live in H13h columns [4096, 4352)
        int p = tid >> 3, j = tid & 7;
        int tok = sTok[p];
#pragma unroll
        for (int k = 0; k < 4; k++) {
            int v = j * 4 + k;
            float val = 0.f;
            if (tok >= 0) {
                int n = (v < 16) ? (4096 + e * LR + v) : (4096 + 128 + e * LR + (v - 16));
                val = __half2float(g_H13h[(size_t)tok * N13 + n]);
            }
            sU[p][v] = val;
        }
    }
    __syncthreads();
    for (int idx = tid; idx < 32 * 128; idx += 256) {
        int p = idx >> 7, col = idx & 127;
        int tok = sTok[p];
        float h1 = 0.f, h3 = 0.f;
        if (tok >= 0) {
            h1 = __half2float(g_H13h[(size_t)tok * N13 + col0 + col]);
            h3 = __half2float(g_H13h[(size_t)tok * N13 + D + col0 + col]);
        }
        float d1 = 0.f, d3 = 0.f;
#pragma unroll
        for (int r = 0; r < LR; r++) {
            d1 += sU[p][r]      * sA1[col * 17 + r];
            d3 += sU[p][16 + r] * sA3[col * 17 + r];
        }
        h1 += ALPHA * d1;
        h3 += ALPHA * d3;
        float s = h1 / (1.f + expf(-h1));
        g_Hph[(size_t)(p0 + p) * D + col0 + col] = __float2half_rn(s * h3);
    }
}

// ---------------- weighted 2-way combine of Hp rows (fp16 out) --------------
__global__ void combine_kernel()
{
    int i = blockIdx.x * 256 + threadIdx.x;   // over TT * (D/8)
    if (i >= TT * (D / 8)) return;
    int t = i >> 8;                            // D/8 = 256
    int c8 = i & 255;
    int pos0 = g_pairPos[t * 2], pos1 = g_pairPos[t * 2 + 1];
    float w0 = g_wtk[t * 2], w1 = g_wtk[t * 2 + 1];
    const __half2* a = (const __half2*)(g_Hph + (size_t)pos0 * D) + c8 * 4;
    const __half2* b = (const __half2*)(g_Hph + (size_t)pos1 * D) + c8 * 4;
    __half2* o = (__half2*)(g_Hc + (size_t)t * D) + c8 * 4;
#pragma unroll
    for (int j = 0; j < 4; j++) {
        float2 av = __half22float2(a[j]);
        float2 bv = __half22float2(b[j]);
        o[j] = __floats2half2_rn(w0 * av.x + w1 * bv.x, w0 * av.y + w1 * bv.y);
    }
}

// ---------------- final: out += ALPHA * sum_k w_k * U2[pos_k] @ A2[e_k]^T ---
__global__ void __launch_bounds__(256) final_delta_kernel(const float* __restrict__ A2,
                                                          float* __restrict__ out)
{
    extern __shared__ float sA2[];        // [e][r][col] = e*2048 + r*128 + col
    __shared__ float sU[64][32];
    __shared__ int   sEl[64][2];
    int col0 = blockIdx.x * 128, t0 = blockIdx.y * 64, tid = threadIdx.x;

#pragma unroll
    for (int it = 0; it < 4; it++) {
        int pc = tid + it * 256;          // (e, col)
        int e = pc >> 7, col = pc & 127;
        const float4* src = (const float4*)(A2 + ((size_t)e * D + col0 + col) * LR);
#pragma unroll
        for (int j = 0; j < 4; j++) {
            float4 v = src[j];
            float* dst = &sA2[e * 2048 + (j * 4) * 128 + col];
            dst[0]   = v.x; dst[128] = v.y; dst[256] = v.z; dst[384] = v.w;
        }
    }
#pragma unroll
    for (int it = 0; it < 8; it++) {
        int idx = tid + it * 256;         // 2048
        int tok = idx >> 5, v = idx & 31;
        int k = v >> 4, r = v & 15;
        int gi = (t0 + tok) * 2 + k;
        int pos = g_pairPos[gi];
        int e   = g_sel[gi];
        sU[tok][v] = g_wtk[gi] * g_U2[(size_t)pos * 128 + e * LR + r];
        if (r == 0) sEl[tok][k] = e;
    }
    __syncthreads();

#pragma unroll 4
    for (int it = 0; it < 32; it++) {
        int idx = tid + it * 256;         // 64*128
        int tok = idx >> 7, col = idx & 127;
        float d = 0.f;
#pragma unroll
        for (int k = 0; k < 2; k++) {
            const float* a2c = &sA2[sEl[tok][k] * 2048 + col];
            const float* u = &sU[tok][k * 16];
#pragma unroll
            for (int r = 0; r < LR; r++) d += u[r] * a2c[r * 128];
        }
        size_t oidx = (size_t)(t0 + tok) * D + col0 + col;
        out[oidx] += ALPHA * d;
    }
}

// ---------------- launch ----------------------------------------------------
extern "C" void kernel_launch(void* const* d_in, const int* in_sizes, int n_in,
                              void* d_out, int out_size)
{
    const float* X     = (const float*)d_in[0];
    const float* Wg    = (const float*)d_in[1];
    const float* Wup   = (const float*)d_in[2];
    const float* Wgate = (const float*)d_in[3];
    const float* Wdown = (const float*)d_in[4];
    const float* A1    = (const float*)d_in[5];
    const float* B1    = (const float*)d_in[6];
    const float* A2    = (const float*)d_in[7];
    const float* B2    = (const float*)d_in[8];
    const float* A3    = (const float*)d_in[9];
    const float* B3    = (const float*)d_in[10];
    float* out = (float*)d_out;

    static __half *pXh = nullptr, *pW13B, *pWdh, *pB2h, *pHph, *pHc, *pH13h;
    static float  *pU2;
    if (!pXh) {
        cudaGetSymbolAddress((void**)&pXh,   g_Xh);
        cudaGetSymbolAddress((void**)&pW13B, g_W13B);
        cudaGetSymbolAddress((void**)&pWdh,  g_Wdh);
        cudaGetSymbolAddress((void**)&pB2h,  g_B2h);
        cudaGetSymbolAddress((void**)&pHph,  g_Hph);
        cudaGetSymbolAddress((void**)&pHc,   g_Hc);
        cudaGetSymbolAddress((void**)&pH13h, g_H13h);
        cudaGetSymbolAddress((void**)&pU2,   g_U2);
        cudaFuncSetAttribute(gemm_h16<__half>,
            cudaFuncAttributeMaxDynamicSharedMemorySize, 3 * STAGE_BY);
        cudaFuncSetAttribute(gemm_h16<float>,
            cudaFuncAttributeMaxDynamicSharedMemorySize, 3 * STAGE_BY);
        cudaFuncSetAttribute(final_delta_kernel,
            cudaFuncAttributeMaxDynamicSharedMemorySize, 65536);
    }
    const int SMB = 3 * STAGE_BY;   // 98304

    reset_kernel<<<(MP + 255) / 256, 256>>>();

    auto cvt = [&](const float* s, __half* d, size_t n) {
        int n4 = (int)(n / 4);
        to_half_kernel<<<(n4 + 255) / 256, 256>>>((const float4*)s, (__half2*)d, n4);
    };
    cvt(X,     pXh,                      (size_t)TT * D);
    cvt(Wup,   pW13B,                    (size_t)D * D);
    cvt(Wgate, pW13B + (size_t)D * D,    (size_t)D * D);
    cvt(B1,    pW13B + (size_t)2 * D * D,(size_t)128 * D);
    cvt(B3,    pW13B + (size_t)2 * D * D + (size_t)128 * D, (size_t)128 * D);
    cvt(Wdown, pWdh,                     (size_t)D * D);
    cvt(B2,    pB2h,                     (size_t)128 * D);

    router_kernel<<<TT * 32 / 256, 256>>>(X, Wg);
    scan_kernel<<<1, 1>>>();
    assign_kernel<<<(TT * 2 + 255) / 256, 256>>>();

    // H13h = Xh @ [Wup;Wgate;B1;B3]^T    [8192 x 4352] fp16
    gemm_h16<__half><<<dim3(N13 / 128, TT / 128), 256, SMB>>>(pXh, pW13B, pH13h, N13, D);

    pair_up_kernel<<<dim3(MP / 32, D / 128), 256>>>(A1, A3);

    combine_kernel<<<TT * (D / 8) / 256, 256>>>();

    // U2 = Hph @ B2^T                    [16640 x 128]
    gemm_h16<float><<<dim3(1, MP / 128), 256, SMB>>>(pHph, pB2h, pU2, 128, D);

    // out_base = Hc @ Wdown^T            [8192 x 2048]  (writes d_out directly)
    gemm_h16<float><<<dim3(D / 128, TT / 128), 256, SMB>>>(pHc, pWdh, out, D, D);

    final_delta_kernel<<<dim3(D / 128, TT / 64), 256, 65536>>>(A2, out);
    (void)in_sizes; (void)n_in; (void)out_size;
}

// round 14
// speedup vs baseline: 1.0745x; 1.0056x over previous
#include <cuda_runtime.h>
#include <cuda_fp16.h>
#include <cstdint>
#include <cstddef>

#define TT 8192
#define D  2048
#define NE 8
#define LR 16
#define MP 16640          // 16384 pairs + 8*32 segment padding
#define ALPHA 2.0f
#define N13 4352          // 2*D + 256 (Wup,Wgate,B1,B3 concatenated)

// ---------------- scratch (device globals; allocation-free) ----------------
__device__ __align__(256) __half g_Xh   [(size_t)TT * D];
__device__ __align__(256) __half g_W13B [(size_t)N13 * D];
__device__ __align__(256) __half g_Wdh  [(size_t)D * D];
__device__ __align__(256) __half g_B2h  [(size_t)128 * D];
__device__ __align__(256) __half g_Hph  [(size_t)MP * D];
__device__ __align__(256) __half g_Hc   [(size_t)TT * D];
__device__ __align__(256) float  g_H13u [(size_t)TT * N13];
__device__ __align__(256) float  g_U2   [(size_t)MP * 128];
__device__ int   g_sel[TT * 2];
__device__ float g_wtk[TT * 2];
__device__ int   g_cnt[NE];
__device__ int   g_off[NE + 1];
__device__ int   g_cur[NE];
__device__ int   g_pairTok[MP];
__device__ int   g_pairPos[TT * 2];

// ---------------- fp32 -> fp16 (rn) -----------------------------------------
__global__ void to_half_kernel(const float4* __restrict__ src,
                               __half2* __restrict__ dst, int n4)
{
    int i = blockIdx.x * 256 + threadIdx.x;
    if (i < n4) {
        float4 v = src[i];
        dst[2 * i]     = __floats2half2_rn(v.x, v.y);
        dst[2 * i + 1] = __floats2half2_rn(v.z, v.w);
    }
}

__global__ void reset_kernel()
{
    int i = blockIdx.x * 256 + threadIdx.x;
    if (i < NE) g_cnt[i] = 0;
    if (i < MP) g_pairTok[i] = -1;
}

// ---------------- router: logits (fp32 accum, matches reference), top-2 -----
__global__ void router_kernel(const float* __restrict__ X,
                              const float* __restrict__ Wg)
{
    int t = (blockIdx.x * blockDim.x + threadIdx.x) >> 5;
    int lane = threadIdx.x & 31;
    if (t >= TT) return;
    const float4* x4 = (const float4*)(X + (size_t)t * D);
    float acc[NE];
#pragma unroll
    for (int e = 0; e < NE; e++) acc[e] = 0.f;
    for (int it = 0; it < 16; it++) {
        float4 xv = x4[it * 32 + lane];
#pragma unroll
        for (int e = 0; e < NE; e++) {
            float4 wv = ((const float4*)(Wg + (size_t)e * D))[it * 32 + lane];
            acc[e] += xv.x * wv.x + xv.y * wv.y + xv.z * wv.z + xv.w * wv.w;
        }
    }
#pragma unroll
    for (int e = 0; e < NE; e++)
#pragma unroll
        for (int o = 16; o > 0; o >>= 1)
            acc[e] += __shfl_xor_sync(0xffffffffu, acc[e], o);
    if (lane == 0) {
        int e0 = 0; float b0 = acc[0];
#pragma unroll
        for (int e = 1; e < NE; e++) if (acc[e] > b0) { b0 = acc[e]; e0 = e; }
        int e1 = -1; float b1 = -1e30f;
#pragma unroll
        for (int e = 0; e < NE; e++)
            if (e != e0 && acc[e] > b1) { b1 = acc[e]; e1 = e; }
        float ew = __expf(b1 - b0);
        float w0 = 1.f / (1.f + ew);
        float w1 = ew * w0;
        g_sel[t * 2] = e0; g_sel[t * 2 + 1] = e1;
        g_wtk[t * 2] = w0; g_wtk[t * 2 + 1] = w1;
        atomicAdd(&g_cnt[e0], 1);
        atomicAdd(&g_cnt[e1], 1);
    }
}

__global__ void scan_kernel()
{
    int o = 0;
    for (int e = 0; e < NE; e++) {
        g_off[e] = o; g_cur[e] = o;
        o += (g_cnt[e] + 31) & ~31;
    }
    g_off[NE] = o;
}

__global__ void assign_kernel()
{
    int i = blockIdx.x * 256 + threadIdx.x;
    if (i < TT * 2) {
        int e = g_sel[i];
        int p = atomicAdd(&g_cur[e], 1);
        g_pairTok[p] = i >> 1;
        g_pairPos[i] = p;
    }
}

__device__ __forceinline__ uint32_t swz(uint32_t off) {
    return off ^ ((off >> 3) & 0x70u);
}

// ---------------- fp16 GEMM 128x128x64: C[M,N] = A[M,K] @ B[N,K]^T ----------
// 8 warps (2m x 4n, warp tile 64x32), 3-stage cp.async, SW128 smem, ldmatrix,
// 2 CTAs/SM, single barrier per K-iteration.
#define STAGE_BY 32768
#define A_BY     16384

template<typename OutT>
__global__ void __launch_bounds__(256, 2) gemm_h16(const __half* __restrict__ A,
                                                   const __half* __restrict__ B,
                                                   OutT* __restrict__ C,
                                                   int Nld, int K)
{
    extern __shared__ char smem[];
    const int tid = threadIdx.x, lane = tid & 31, wid = tid >> 5;
    const int wm = wid & 1, wn = wid >> 1;
    uint32_t sb;
    asm("{ .reg .u64 t; cvta.to.shared.u64 t, %1; cvt.u32.u64 %0, t; }"
        : "=r"(sb) : "l"(smem));

    const __half* Ab = A + (size_t)blockIdx.y * 128 * K;
    const __half* Bb = B + (size_t)blockIdx.x * 128 * K;
    const int KT = K >> 6;

    auto load_tile = [&](int kt, int st) {
        uint32_t base = sb + st * STAGE_BY;
#pragma unroll
        for (int i = 0; i < 8; i++) {
            int f = tid + i * 256;          // 2048 chunks of 16B; 8 per row
            const __half* src;
            uint32_t off;
            if (f < 1024) {
                int r = f >> 3, q = f & 7;
                src = Ab + (size_t)r * K + kt * 64 + q * 8;
                off = swz((uint32_t)(r * 128 + q * 16));
            } else {
                int f2 = f - 1024;
                int r = f2 >> 3, q = f2 & 7;
                src = Bb + (size_t)r * K + kt * 64 + q * 8;
                off = A_BY + swz((uint32_t)(r * 128 + q * 16));
            }
            asm volatile("cp.async.cg.shared.global [%0], [%1], 16;"
                         :: "r"(base + off), "l"(src));
        }
        asm volatile("cp.async.commit_group;");
    };

    float acc[4][4][4];
#pragma unroll
    for (int i = 0; i < 4; i++)
#pragma unroll
        for (int j = 0; j < 4; j++)
#pragma unroll
            for (int k = 0; k < 4; k++) acc[i][j][k] = 0.f;

    load_tile(0, 0);
    load_tile(1, 1);

    const int lrow = lane & 15, lcol = (lane >> 4) << 4;

#pragma unroll 1
    for (int kt = 0; kt < KT; kt++) {
        if (kt + 1 < KT) asm volatile("cp.async.wait_group 1;");
        else             asm volatile("cp.async.wait_group 0;");
        __syncthreads();                     // orders compute(kt-1) vs load(kt+2) too
        if (kt + 2 < KT) load_tile(kt + 2, (kt + 2) % 3);

        uint32_t sA = sb + (kt % 3) * STAGE_BY;
        uint32_t sB = sA + A_BY;
#pragma unroll
        for (int kk = 0; kk < 4; kk++) {
            uint32_t af[4][4], bf[4][2];
#pragma unroll
            for (int mi = 0; mi < 4; mi++) {
                int row = wm * 64 + mi * 16 + lrow;
                uint32_t ad = sA + swz((uint32_t)(row * 128 + kk * 32 + lcol));
                asm volatile(
                    "ldmatrix.sync.aligned.m8n8.x4.shared.b16 {%0,%1,%2,%3}, [%4];"
                    : "=r"(af[mi][0]), "=r"(af[mi][1]),
                      "=r"(af[mi][2]), "=r"(af[mi][3]) : "r"(ad));
            }
#pragma unroll
            for (int bi = 0; bi < 2; bi++) {
                int row = wn * 32 + bi * 16 + lrow;
                uint32_t bd = sB + swz((uint32_t)(row * 128 + kk * 32 + lcol));
                uint32_t r0, r1, r2, r3;
                asm volatile(
                    "ldmatrix.sync.aligned.m8n8.x4.shared.b16 {%0,%1,%2,%3}, [%4];"
                    : "=r"(r0), "=r"(r1), "=r"(r2), "=r"(r3) : "r"(bd));
                bf[2 * bi][0] = r0;     bf[2 * bi][1] = r2;
                bf[2 * bi + 1][0] = r1; bf[2 * bi + 1][1] = r3;
            }
#pragma unroll
            for (int mi = 0; mi < 4; mi++)
#pragma unroll
                for (int ni = 0; ni < 4; ni++)
                    asm volatile(
                        "mma.sync.aligned.m16n8k16.row.col.f32.f16.f16.f32 "
                        "{%0,%1,%2,%3}, {%4,%5,%6,%7}, {%8,%9}, {%0,%1,%2,%3};"
                        : "+f"(acc[mi][ni][0]), "+f"(acc[mi][ni][1]),
                          "+f"(acc[mi][ni][2]), "+f"(acc[mi][ni][3])
                        : "r"(af[mi][0]), "r"(af[mi][1]),
                          "r"(af[mi][2]), "r"(af[mi][3]),
                          "r"(bf[ni][0]), "r"(bf[ni][1]));
        }
    }

    const int g = lane >> 2, c = lane & 3;
    int mBase = blockIdx.y * 128 + wm * 64;
    int nBase = blockIdx.x * 128 + wn * 32;
#pragma unroll
    for (int mi = 0; mi < 4; mi++)
#pragma unroll
        for (int ni = 0; ni < 4; ni++) {
            int row0 = mBase + mi * 16 + g;
            int col  = nBase + ni * 8 + c * 2;
            if constexpr (sizeof(OutT) == 2) {
                *(__half2*)&C[(size_t)row0 * Nld + col] =
                    __floats2half2_rn(acc[mi][ni][0], acc[mi][ni][1]);
                *(__half2*)&C[(size_t)(row0 + 8) * Nld + col] =
                    __floats2half2_rn(acc[mi][ni][2], acc[mi][ni][3]);
            } else {
                *(float2*)&C[(size_t)row0 * Nld + col] =
                    make_float2(acc[mi][ni][0], acc[mi][ni][1]);
                *(float2*)&C[(size_t)(row0 + 8) * Nld + col] =
                    make_float2(acc[mi][ni][2], acc[mi][ni][3]);
            }
        }
}

// ---------------- per-pair LoRA up deltas + SwiGLU (fp32 in, fp16 out) ------
__global__ void __launch_bounds__(256) pair_up_kernel(const float* __restrict__ A1,
                                                      const float* __restrict__ A3)
{
    __shared__ float sA1[128 * 17], sA3[128 * 17];
    __shared__ float sU[32][33];
    __shared__ int   sTok[32];
    __shared__ int   sE;
    int p0 = blockIdx.x * 32, col0 = blockIdx.y * 128, tid = threadIdx.x;
    if (tid < 32) sTok[tid] = g_pairTok[p0 + tid];
    if (tid == 0) {
        int e = 0;
        while (e < NE - 1 && g_off[e + 1] <= p0) e++;
        sE = e;
    }
    __syncthreads();
    int e = sE;
    {
        int col = tid >> 1, half = tid & 1;
        const float* a1 = A1 + ((size_t)e * D + col0 + col) * LR + half * 8;
        const float* a3 = A3 + ((size_t)e * D + col0 + col) * LR + half * 8;
        float4 v0 = ((const float4*)a1)[0], v1 = ((const float4*)a1)[1];
        float* d1 = &sA1[col * 17 + half * 8];
        d1[0]=v0.x; d1[1]=v0.y; d1[2]=v0.z; d1[3]=v0.w;
        d1[4]=v1.x; d1[5]=v1.y; d1[6]=v1.z; d1[7]=v1.w;
        v0 = ((const float4*)a3)[0]; v1 = ((const float4*)a3)[1];
        float* d3 = &sA3[col * 17 + half * 8];
        d3[0]=v0.x; d3[1]=v0.y; d3[2]=v0.z; d3[3]=v0.w;
        d3[4]=v1.x; d3[5]=v1.y; d3[6]=v1.z; d3[7]=v1.w;
    }
    {   // per-pair LoRA-up values live in H13u columns [4096, 4352)
        int p = tid >> 3, j = tid & 7;
        int tok = sTok[p];
#pragma unroll
        for (int k = 0; k < 4; k++) {
            int v = j * 4 + k;
            float val = 0.f;
            if (tok >= 0) {
                int n = (v < 16) ? (4096 + e * LR + v) : (4096 + 128 + e * LR + (v - 16));
                val = g_H13u[(size_t)tok * N13 + n];
            }
            sU[p][v] = val;
        }
    }
    __syncthreads();
    for (int idx = tid; idx < 32 * 128; idx += 256) {
        int p = idx >> 7, col = idx & 127;
        int tok = sTok[p];
        float h1 = 0.f, h3 = 0.f;
        if (tok >= 0) {
            h1 = g_H13u[(size_t)tok * N13 + col0 + col];
            h3 = g_H13u[(size_t)tok * N13 + D + col0 + col];
        }
        float d1 = 0.f, d3 = 0.f;
#pragma unroll
        for (int r = 0; r < LR; r++) {
            d1 += sU[p][r]      * sA1[col * 17 + r];
            d3 += sU[p][16 + r] * sA3[col * 17 + r];
        }
        h1 += ALPHA * d1;
        h3 += ALPHA * d3;
        float s = h1 / (1.f + expf(-h1));
        g_Hph[(size_t)(p0 + p) * D + col0 + col] = __float2half_rn(s * h3);
    }
}

// ---------------- weighted 2-way combine of Hp rows (fp16 out) --------------
__global__ void combine_kernel()
{
    int i = blockIdx.x * 256 + threadIdx.x;   // over TT * (D/8)
    if (i >= TT * (D / 8)) return;
    int t = i >> 8;                            // D/8 = 256
    int c8 = i & 255;
    int pos0 = g_pairPos[t * 2], pos1 = g_pairPos[t * 2 + 1];
    float w0 = g_wtk[t * 2], w1 = g_wtk[t * 2 + 1];
    const __half2* a = (const __half2*)(g_Hph + (size_t)pos0 * D) + c8 * 4;
    const __half2* b = (const __half2*)(g_Hph + (size_t)pos1 * D) + c8 * 4;
    __half2* o = (__half2*)(g_Hc + (size_t)t * D) + c8 * 4;
#pragma unroll
    for (int j = 0; j < 4; j++) {
        float2 av = __half22float2(a[j]);
        float2 bv = __half22float2(b[j]);
        o[j] = __floats2half2_rn(w0 * av.x + w1 * bv.x, w0 * av.y + w1 * bv.y);
    }
}

// ---------------- final: out += ALPHA * sum_k w_k * U2[pos_k] @ A2[e_k]^T ---
__global__ void __launch_bounds__(256) final_delta_kernel(const float* __restrict__ A2,
                                                          float* __restrict__ out)
{
    extern __shared__ float sA2[];        // [e][r][col] = e*2048 + r*128 + col
    __shared__ float sU[64][32];
    __shared__ int   sEl[64][2];
    int col0 = blockIdx.x * 128, t0 = blockIdx.y * 64, tid = threadIdx.x;

#pragma unroll
    for (int it = 0; it < 4; it++) {
        int pc = tid + it * 256;          // (e, col)
        int e = pc >> 7, col = pc & 127;
        const float4* src = (const float4*)(A2 + ((size_t)e * D + col0 + col) * LR);
#pragma unroll
        for (int j = 0; j < 4; j++) {
            float4 v = src[j];
            float* dst = &sA2[e * 2048 + (j * 4) * 128 + col];
            dst[0]   = v.x; dst[128] = v.y; dst[256] = v.z; dst[384] = v.w;
        }
    }
#pragma unroll
    for (int it = 0; it < 8; it++) {
        int idx = tid + it * 256;         // 2048
        int tok = idx >> 5, v = idx & 31;
        int k = v >> 4, r = v & 15;
        int gi = (t0 + tok) * 2 + k;
        int pos = g_pairPos[gi];
        int e   = g_sel[gi];
        sU[tok][v] = g_wtk[gi] * g_U2[(size_t)pos * 128 + e * LR + r];
        if (r == 0) sEl[tok][k] = e;
    }
    __syncthreads();

#pragma unroll 4
    for (int it = 0; it < 32; it++) {
        int idx = tid + it * 256;         // 64*128
        int tok = idx >> 7, col = idx & 127;
        float d = 0.f;
#pragma unroll
        for (int k = 0; k < 2; k++) {
            const float* a2c = &sA2[sEl[tok][k] * 2048 + col];
            const float* u = &sU[tok][k * 16];
#pragma unroll
            for (int r = 0; r < LR; r++) d += u[r] * a2c[r * 128];
        }
        size_t oidx = (size_t)(t0 + tok) * D + col0 + col;
        out[oidx] += ALPHA * d;
    }
}

// ---------------- launch ----------------------------------------------------
extern "C" void kernel_launch(void* const* d_in, const int* in_sizes, int n_in,
                              void* d_out, int out_size)
{
    const float* X     = (const float*)d_in[0];
    const float* Wg    = (const float*)d_in[1];
    const float* Wup   = (const float*)d_in[2];
    const float* Wgate = (const float*)d_in[3];
    const float* Wdown = (const float*)d_in[4];
    const float* A1    = (const float*)d_in[5];
    const float* B1    = (const float*)d_in[6];
    const float* A2    = (const float*)d_in[7];
    const float* B2    = (const float*)d_in[8];
    const float* A3    = (const float*)d_in[9];
    const float* B3    = (const float*)d_in[10];
    float* out = (float*)d_out;

    static __half *pXh = nullptr, *pW13B, *pWdh, *pB2h, *pHph, *pHc;
    static float  *pH13u, *pU2;
    if (!pXh) {
        cudaGetSymbolAddress((void**)&pXh,   g_Xh);
        cudaGetSymbolAddress((void**)&pW13B, g_W13B);
        cudaGetSymbolAddress((void**)&pWdh,  g_Wdh);
        cudaGetSymbolAddress((void**)&pB2h,  g_B2h);
        cudaGetSymbolAddress((void**)&pHph,  g_Hph);
        cudaGetSymbolAddress((void**)&pHc,   g_Hc);
        cudaGetSymbolAddress((void**)&pH13u, g_H13u);
        cudaGetSymbolAddress((void**)&pU2,   g_U2);
        cudaFuncSetAttribute(gemm_h16<float>,
            cudaFuncAttributeMaxDynamicSharedMemorySize, 3 * STAGE_BY);
        cudaFuncSetAttribute(final_delta_kernel,
            cudaFuncAttributeMaxDynamicSharedMemorySize, 65536);
    }
    const int SMB = 3 * STAGE_BY;   // 98304

    auto cvt = [&](const float* s, __half* d, size_t n) {
        int n4 = (int)(n / 4);
        to_half_kernel<<<(n4 + 255) / 256, 256>>>((const float4*)s, (__half2*)d, n4);
    };

    // Launches 1-5: converts feeding GEMM1; launch 6 = GEMM1 (ncu -s 5 -c 1 slot)
    cvt(X,     pXh,                      (size_t)TT * D);
    cvt(Wup,   pW13B,                    (size_t)D * D);
    cvt(Wgate, pW13B + (size_t)D * D,    (size_t)D * D);
    cvt(B1,    pW13B + (size_t)2 * D * D,(size_t)128 * D);
    cvt(B3,    pW13B + (size_t)2 * D * D + (size_t)128 * D, (size_t)128 * D);

    // H13u = Xh @ [Wup;Wgate;B1;B3]^T    [8192 x 4352] fp32
    gemm_h16<float><<<dim3(N13 / 128, TT / 128), 256, SMB>>>(pXh, pW13B, pH13u, N13, D);

    cvt(Wdown, pWdh,                     (size_t)D * D);
    cvt(B2,    pB2h,                     (size_t)128 * D);

    reset_kernel<<<(MP + 255) / 256, 256>>>();
    router_kernel<<<TT * 32 / 256, 256>>>(X, Wg);
    scan_kernel<<<1, 1>>>();
    assign_kernel<<<(TT * 2 + 255) / 256, 256>>>();

    pair_up_kernel<<<dim3(MP / 32, D / 128), 256>>>(A1, A3);

    combine_kernel<<<TT * (D / 8) / 256, 256>>>();

    // U2 = Hph @ B2^T                    [16640 x 128]
    gemm_h16<float><<<dim3(1, MP / 128), 256, SMB>>>(pHph, pB2h, pU2, 128, D);

    // out_base = Hc @ Wdown^T            [8192 x 2048]  (writes d_out directly)
    gemm_h16<float><<<dim3(D / 128, TT / 128), 256, SMB>>>(pHc, pWdh, out, D, D);

    final_delta_kernel<<<dim3(D / 128, TT / 64), 256, 65536>>>(A2, out);
    (void)in_sizes; (void)n_in; (void)out_size;
}

// round 16
// speedup vs baseline: 1.1918x; 1.1092x over previous
#include <cuda_runtime.h>
#include <cuda_fp16.h>
#include <cstdint>
#include <cstddef>

#define TT 8192
#define D  2048
#define NE 8
#define LR 16
#define MP 16640          // 16384 pairs + 8*32 segment padding
#define ALPHA 2.0f
#define N13 4352          // 2*D + 256 (Wup,Wgate,B1,B3 concatenated)

// ---------------- scratch (device globals; allocation-free) ----------------
__device__ __align__(256) __half g_Xh   [(size_t)TT * D];
__device__ __align__(256) __half g_W13B [(size_t)N13 * D];
__device__ __align__(256) __half g_Wdh  [(size_t)D * D];
__device__ __align__(256) __half g_B2h  [(size_t)128 * D];
__device__ __align__(256) __half g_Hph  [(size_t)MP * D];
__device__ __align__(256) __half g_Hc   [(size_t)TT * D];
__device__ __align__(256) __half g_H13h [(size_t)TT * N13];
__device__ __align__(256) float  g_U2   [(size_t)MP * 128];
__device__ int   g_sel[TT * 2];
__device__ float g_wtk[TT * 2];
__device__ int   g_cnt[NE];
__device__ int   g_off[NE + 1];
__device__ int   g_cur[NE];
__device__ int   g_pairTok[MP];
__device__ int   g_pairPos[TT * 2];

// ---------------- fp32 -> fp16 (rn), 4-way MLP ------------------------------
__global__ void to_half_kernel(const float4* __restrict__ src,
                               __half2* __restrict__ dst, int n4)
{
    int base = blockIdx.x * 1024 + threadIdx.x;
#pragma unroll
    for (int k = 0; k < 4; k++) {
        int i = base + k * 256;
        if (i < n4) {
            float4 v = src[i];
            dst[2 * i]     = __floats2half2_rn(v.x, v.y);
            dst[2 * i + 1] = __floats2half2_rn(v.z, v.w);
        }
    }
}

__global__ void reset_kernel()
{
    int i = blockIdx.x * 256 + threadIdx.x;
    if (i < NE) g_cnt[i] = 0;
    if (i < MP) g_pairTok[i] = -1;
}

// ---------------- router: logits (fp32 accum, matches reference), top-2 -----
__global__ void router_kernel(const float* __restrict__ X,
                              const float* __restrict__ Wg)
{
    int t = (blockIdx.x * blockDim.x + threadIdx.x) >> 5;
    int lane = threadIdx.x & 31;
    if (t >= TT) return;
    const float4* x4 = (const float4*)(X + (size_t)t * D);
    float acc[NE];
#pragma unroll
    for (int e = 0; e < NE; e++) acc[e] = 0.f;
    for (int it = 0; it < 16; it++) {
        float4 xv = x4[it * 32 + lane];
#pragma unroll
        for (int e = 0; e < NE; e++) {
            float4 wv = ((const float4*)(Wg + (size_t)e * D))[it * 32 + lane];
            acc[e] += xv.x * wv.x + xv.y * wv.y + xv.z * wv.z + xv.w * wv.w;
        }
    }
#pragma unroll
    for (int e = 0; e < NE; e++)
#pragma unroll
        for (int o = 16; o > 0; o >>= 1)
            acc[e] += __shfl_xor_sync(0xffffffffu, acc[e], o);
    if (lane == 0) {
        int e0 = 0; float b0 = acc[0];
#pragma unroll
        for (int e = 1; e < NE; e++) if (acc[e] > b0) { b0 = acc[e]; e0 = e; }
        int e1 = -1; float b1 = -1e30f;
#pragma unroll
        for (int e = 0; e < NE; e++)
            if (e != e0 && acc[e] > b1) { b1 = acc[e]; e1 = e; }
        float ew = __expf(b1 - b0);
        float w0 = 1.f / (1.f + ew);
        float w1 = ew * w0;
        g_sel[t * 2] = e0; g_sel[t * 2 + 1] = e1;
        g_wtk[t * 2] = w0; g_wtk[t * 2 + 1] = w1;
        atomicAdd(&g_cnt[e0], 1);
        atomicAdd(&g_cnt[e1], 1);
    }
}

__global__ void scan_kernel()
{
    int o = 0;
    for (int e = 0; e < NE; e++) {
        g_off[e] = o; g_cur[e] = o;
        o += (g_cnt[e] + 31) & ~31;
    }
    g_off[NE] = o;
}

__global__ void assign_kernel()
{
    int i = blockIdx.x * 256 + threadIdx.x;
    if (i < TT * 2) {
        int e = g_sel[i];
        int p = atomicAdd(&g_cur[e], 1);
        g_pairTok[p] = i >> 1;
        g_pairPos[i] = p;
    }
}

__device__ __forceinline__ uint32_t swz(uint32_t off) {
    return off ^ ((off >> 3) & 0x70u);
}
__device__ __forceinline__ uint32_t s2u(const void* p) {
    uint32_t a;
    asm("{ .reg .u64 t; cvta.to.shared.u64 t, %1; cvt.u32.u64 %0, t; }"
        : "=r"(a) : "l"(p));
    return a;
}

// ---------------- fp16 GEMM 128x128x64: C[M,N] = A[M,K] @ B[N,K]^T ----------
#define STAGE_BY 32768
#define A_BY     16384

template<typename OutT>
__global__ void __launch_bounds__(256, 2) gemm_h16(const __half* __restrict__ A,
                                                   const __half* __restrict__ B,
                                                   OutT* __restrict__ C,
                                                   int Nld, int K)
{
    extern __shared__ char smem[];
    const int tid = threadIdx.x, lane = tid & 31, wid = tid >> 5;
    const int wm = wid & 1, wn = wid >> 1;
    uint32_t sb = s2u(smem);

    const __half* Ab = A + (size_t)blockIdx.y * 128 * K;
    const __half* Bb = B + (size_t)blockIdx.x * 128 * K;
    const int KT = K >> 6;

    auto load_tile = [&](int kt, int st) {
        uint32_t base = sb + st * STAGE_BY;
#pragma unroll
        for (int i = 0; i < 8; i++) {
            int f = tid + i * 256;
            const __half* src;
            uint32_t off;
            if (f < 1024) {
                int r = f >> 3, q = f & 7;
                src = Ab + (size_t)r * K + kt * 64 + q * 8;
                off = swz((uint32_t)(r * 128 + q * 16));
            } else {
                int f2 = f - 1024;
                int r = f2 >> 3, q = f2 & 7;
                src = Bb + (size_t)r * K + kt * 64 + q * 8;
                off = A_BY + swz((uint32_t)(r * 128 + q * 16));
            }
            asm volatile("cp.async.cg.shared.global [%0], [%1], 16;"
                         :: "r"(base + off), "l"(src));
        }
        asm volatile("cp.async.commit_group;");
    };

    float acc[4][4][4];
#pragma unroll
    for (int i = 0; i < 4; i++)
#pragma unroll
        for (int j = 0; j < 4; j++)
#pragma unroll
            for (int k = 0; k < 4; k++) acc[i][j][k] = 0.f;

    load_tile(0, 0);
    load_tile(1, 1);

    const int lrow = lane & 15, lcol = (lane >> 4) << 4;

#pragma unroll 1
    for (int kt = 0; kt < KT; kt++) {
        if (kt + 1 < KT) asm volatile("cp.async.wait_group 1;");
        else             asm volatile("cp.async.wait_group 0;");
        __syncthreads();
        if (kt + 2 < KT) load_tile(kt + 2, (kt + 2) % 3);

        uint32_t sA = sb + (kt % 3) * STAGE_BY;
        uint32_t sB = sA + A_BY;
#pragma unroll
        for (int kk = 0; kk < 4; kk++) {
            uint32_t af[4][4], bf[4][2];
#pragma unroll
            for (int mi = 0; mi < 4; mi++) {
                int row = wm * 64 + mi * 16 + lrow;
                uint32_t ad = sA + swz((uint32_t)(row * 128 + kk * 32 + lcol));
                asm volatile(
                    "ldmatrix.sync.aligned.m8n8.x4.shared.b16 {%0,%1,%2,%3}, [%4];"
                    : "=r"(af[mi][0]), "=r"(af[mi][1]),
                      "=r"(af[mi][2]), "=r"(af[mi][3]) : "r"(ad));
            }
#pragma unroll
            for (int bi = 0; bi < 2; bi++) {
                int row = wn * 32 + bi * 16 + lrow;
                uint32_t bd = sB + swz((uint32_t)(row * 128 + kk * 32 + lcol));
                uint32_t r0, r1, r2, r3;
                asm volatile(
                    "ldmatrix.sync.aligned.m8n8.x4.shared.b16 {%0,%1,%2,%3}, [%4];"
                    : "=r"(r0), "=r"(r1), "=r"(r2), "=r"(r3) : "r"(bd));
                bf[2 * bi][0] = r0;     bf[2 * bi][1] = r2;
                bf[2 * bi + 1][0] = r1; bf[2 * bi + 1][1] = r3;
            }
#pragma unroll
            for (int mi = 0; mi < 4; mi++)
#pragma unroll
                for (int ni = 0; ni < 4; ni++)
                    asm volatile(
                        "mma.sync.aligned.m16n8k16.row.col.f32.f16.f16.f32 "
                        "{%0,%1,%2,%3}, {%4,%5,%6,%7}, {%8,%9}, {%0,%1,%2,%3};"
                        : "+f"(acc[mi][ni][0]), "+f"(acc[mi][ni][1]),
                          "+f"(acc[mi][ni][2]), "+f"(acc[mi][ni][3])
                        : "r"(af[mi][0]), "r"(af[mi][1]),
                          "r"(af[mi][2]), "r"(af[mi][3]),
                          "r"(bf[ni][0]), "r"(bf[ni][1]));
        }
    }

    const int g = lane >> 2, c = lane & 3;
    int mBase = blockIdx.y * 128 + wm * 64;
    int nBase = blockIdx.x * 128 + wn * 32;
#pragma unroll
    for (int mi = 0; mi < 4; mi++)
#pragma unroll
        for (int ni = 0; ni < 4; ni++) {
            int row0 = mBase + mi * 16 + g;
            int col  = nBase + ni * 8 + c * 2;
            if constexpr (sizeof(OutT) == 2) {
                *(__half2*)&C[(size_t)row0 * Nld + col] =
                    __floats2half2_rn(acc[mi][ni][0], acc[mi][ni][1]);
                *(__half2*)&C[(size_t)(row0 + 8) * Nld + col] =
                    __floats2half2_rn(acc[mi][ni][2], acc[mi][ni][3]);
            } else {
                *(float2*)&C[(size_t)row0 * Nld + col] =
                    make_float2(acc[mi][ni][0], acc[mi][ni][1]);
                *(float2*)&C[(size_t)(row0 + 8) * Nld + col] =
                    make_float2(acc[mi][ni][2], acc[mi][ni][3]);
            }
        }
}

// ---------------- pair_up v3: tensor-core LoRA delta + SwiGLU ---------------
// Block: 32 pairs x 128 cols. Delta = U(32x16) @ A^T(16x128) via m16n8k16.
// 8 warps: wm = m-tile (16 pairs), wn = n-tile (32 cols).
__global__ void __launch_bounds__(256) pair_up_kernel(const float* __restrict__ A1,
                                                      const float* __restrict__ A3)
{
    __shared__ __align__(16) __half sU1h[32 * 16];
    __shared__ __align__(16) __half sU3h[32 * 16];
    __shared__ __align__(16) __half sA1h[128 * 16];
    __shared__ __align__(16) __half sA3h[128 * 16];
    __shared__ int sTok[32];
    __shared__ int sE;
    int p0 = blockIdx.x * 32, col0 = blockIdx.y * 128, tid = threadIdx.x;
    const int lane = tid & 31, wid = tid >> 5;
    if (tid < 32) sTok[tid] = g_pairTok[p0 + tid];
    if (tid == 0) {
        int e = 0;
        while (e < NE - 1 && g_off[e + 1] <= p0) e++;
        sE = e;
    }
    __syncthreads();
    int e = sE;
    {   // stage A1/A3 [128 cols x 16 r] fp32 -> fp16
        int col = tid >> 1, half = tid & 1;
        const float4* a1 = (const float4*)(A1 + ((size_t)e * D + col0 + col) * LR + half * 8);
        const float4* a3 = (const float4*)(A3 + ((size_t)e * D + col0 + col) * LR + half * 8);
        float4 v0 = a1[0], v1 = a1[1];
        __half2* d1 = (__half2*)&sA1h[col * 16 + half * 8];
        d1[0] = __floats2half2_rn(v0.x, v0.y); d1[1] = __floats2half2_rn(v0.z, v0.w);
        d1[2] = __floats2half2_rn(v1.x, v1.y); d1[3] = __floats2half2_rn(v1.z, v1.w);
        v0 = a3[0]; v1 = a3[1];
        __half2* d3 = (__half2*)&sA3h[col * 16 + half * 8];
        d3[0] = __floats2half2_rn(v0.x, v0.y); d3[1] = __floats2half2_rn(v0.z, v0.w);
        d3[2] = __floats2half2_rn(v1.x, v1.y); d3[3] = __floats2half2_rn(v1.z, v1.w);
    }
    {   // stage U (fp16 from H13h cols [4096,4352)): 32 pairs x 16 x2
        int p = tid >> 3, j = tid & 7;
        int tok = sTok[p];
        __half2 u1 = __floats2half2_rn(0.f, 0.f), u3 = u1;
        if (tok >= 0) {
            u1 = *(const __half2*)&g_H13h[(size_t)tok * N13 + 4096 + e * LR + j * 2];
            u3 = *(const __half2*)&g_H13h[(size_t)tok * N13 + 4096 + 128 + e * LR + j * 2];
        }
        *(__half2*)&sU1h[p * 16 + j * 2] = u1;
        *(__half2*)&sU3h[p * 16 + j * 2] = u3;
    }
    __syncthreads();

    const int wm = wid & 1, wn = wid >> 1;
    const int lrow = lane & 15, lcol = (lane >> 4) << 4;   // bytes
    uint32_t su1 = s2u(sU1h), su3 = s2u(sU3h);
    uint32_t sa1 = s2u(sA1h), sa3 = s2u(sA3h);

    uint32_t af1[4], af3[4];
    asm volatile("ldmatrix.sync.aligned.m8n8.x4.shared.b16 {%0,%1,%2,%3}, [%4];"
        : "=r"(af1[0]), "=r"(af1[1]), "=r"(af1[2]), "=r"(af1[3])
        : "r"(su1 + (uint32_t)((wm * 16 + lrow) * 32 + lcol)));
    asm volatile("ldmatrix.sync.aligned.m8n8.x4.shared.b16 {%0,%1,%2,%3}, [%4];"
        : "=r"(af3[0]), "=r"(af3[1]), "=r"(af3[2]), "=r"(af3[3])
        : "r"(su3 + (uint32_t)((wm * 16 + lrow) * 32 + lcol)));

    uint32_t bf1[4][2], bf3[4][2];
#pragma unroll
    for (int bi = 0; bi < 2; bi++) {
        uint32_t ad = (uint32_t)((wn * 32 + bi * 16 + lrow) * 32 + lcol);
        uint32_t r0, r1, r2, r3;
        asm volatile("ldmatrix.sync.aligned.m8n8.x4.shared.b16 {%0,%1,%2,%3}, [%4];"
            : "=r"(r0), "=r"(r1), "=r"(r2), "=r"(r3) : "r"(sa1 + ad));
        bf1[2 * bi][0] = r0;     bf1[2 * bi][1] = r2;
        bf1[2 * bi + 1][0] = r1; bf1[2 * bi + 1][1] = r3;
        asm volatile("ldmatrix.sync.aligned.m8n8.x4.shared.b16 {%0,%1,%2,%3}, [%4];"
            : "=r"(r0), "=r"(r1), "=r"(r2), "=r"(r3) : "r"(sa3 + ad));
        bf3[2 * bi][0] = r0;     bf3[2 * bi][1] = r2;
        bf3[2 * bi + 1][0] = r1; bf3[2 * bi + 1][1] = r3;
    }

    float d1a[4][4], d3a[4][4];
#pragma unroll
    for (int ni = 0; ni < 4; ni++) {
#pragma unroll
        for (int k = 0; k < 4; k++) { d1a[ni][k] = 0.f; d3a[ni][k] = 0.f; }
        asm volatile(
            "mma.sync.aligned.m16n8k16.row.col.f32.f16.f16.f32 "
            "{%0,%1,%2,%3}, {%4,%5,%6,%7}, {%8,%9}, {%0,%1,%2,%3};"
            : "+f"(d1a[ni][0]), "+f"(d1a[ni][1]), "+f"(d1a[ni][2]), "+f"(d1a[ni][3])
            : "r"(af1[0]), "r"(af1[1]), "r"(af1[2]), "r"(af1[3]),
              "r"(bf1[ni][0]), "r"(bf1[ni][1]));
        asm volatile(
            "mma.sync.aligned.m16n8k16.row.col.f32.f16.f16.f32 "
            "{%0,%1,%2,%3}, {%4,%5,%6,%7}, {%8,%9}, {%0,%1,%2,%3};"
            : "+f"(d3a[ni][0]), "+f"(d3a[ni][1]), "+f"(d3a[ni][2]), "+f"(d3a[ni][3])
            : "r"(af3[0]), "r"(af3[1]), "r"(af3[2]), "r"(af3[3]),
              "r"(bf3[ni][0]), "r"(bf3[ni][1]));
    }

    // epilogue: rows = pairs, cols = feature cols
    const int g = lane >> 2, c = lane & 3;
#pragma unroll
    for (int half = 0; half < 2; half++) {
        int pr = wm * 16 + g + half * 8;
        int pair = p0 + pr;
        int tok = sTok[pr];
#pragma unroll
        for (int ni = 0; ni < 4; ni++) {
            int cc = wn * 32 + ni * 8 + c * 2;
            __half2* dst = (__half2*)&g_Hph[(size_t)pair * D + col0 + cc];
            if (tok >= 0) {
                __half2 h1v = *(const __half2*)&g_H13h[(size_t)tok * N13 + col0 + cc];
                __half2 h3v = *(const __half2*)&g_H13h[(size_t)tok * N13 + D + col0 + cc];
                float h1x = __low2float(h1v)  + ALPHA * d1a[ni][half * 2];
                float h1y = __high2float(h1v) + ALPHA * d1a[ni][half * 2 + 1];
                float h3x = __low2float(h3v)  + ALPHA * d3a[ni][half * 2];
                float h3y = __high2float(h3v) + ALPHA * d3a[ni][half * 2 + 1];
                float ox = (h1x / (1.f + expf(-h1x))) * h3x;
                float oy = (h1y / (1.f + expf(-h1y))) * h3y;
                *dst = __floats2half2_rn(ox, oy);
            } else {
                *dst = __floats2half2_rn(0.f, 0.f);
            }
        }
    }
}

// ---------------- weighted 2-way combine of Hp rows (fp16 out) --------------
__global__ void combine_kernel()
{
    int i = blockIdx.x * 256 + threadIdx.x;   // over TT * (D/8)
    if (i >= TT * (D / 8)) return;
    int t = i >> 8;
    int c8 = i & 255;
    int pos0 = g_pairPos[t * 2], pos1 = g_pairPos[t * 2 + 1];
    float w0 = g_wtk[t * 2], w1 = g_wtk[t * 2 + 1];
    const __half2* a = (const __half2*)(g_Hph + (size_t)pos0 * D) + c8 * 4;
    const __half2* b = (const __half2*)(g_Hph + (size_t)pos1 * D) + c8 * 4;
    __half2* o = (__half2*)(g_Hc + (size_t)t * D) + c8 * 4;
#pragma unroll
    for (int j = 0; j < 4; j++) {
        float2 av = __half22float2(a[j]);
        float2 bv = __half22float2(b[j]);
        o[j] = __floats2half2_rn(w0 * av.x + w1 * bv.x, w0 * av.y + w1 * bv.y);
    }
}

// ---------------- final: out += ALPHA * sum_k w_k * U2[pos_k] @ A2[e_k]^T ---
__global__ void __launch_bounds__(256) final_delta_kernel(const float* __restrict__ A2,
                                                          float* __restrict__ out)
{
    extern __shared__ float sA2[];        // [e][r][col] = e*2048 + r*128 + col
    __shared__ float sU[64][32];
    __shared__ int   sEl[64][2];
    int col0 = blockIdx.x * 128, t0 = blockIdx.y * 64, tid = threadIdx.x;

#pragma unroll
    for (int it = 0; it < 4; it++) {
        int pc = tid + it * 256;
        int e = pc >> 7, col = pc & 127;
        const float4* src = (const float4*)(A2 + ((size_t)e * D + col0 + col) * LR);
#pragma unroll
        for (int j = 0; j < 4; j++) {
            float4 v = src[j];
            float* dst = &sA2[e * 2048 + (j * 4) * 128 + col];
            dst[0]   = v.x; dst[128] = v.y; dst[256] = v.z; dst[384] = v.w;
        }
    }
#pragma unroll
    for (int it = 0; it < 8; it++) {
        int idx = tid + it * 256;
        int tok = idx >> 5, v = idx & 31;
        int k = v >> 4, r = v & 15;
        int gi = (t0 + tok) * 2 + k;
        int pos = g_pairPos[gi];
        int e   = g_sel[gi];
        sU[tok][v] = g_wtk[gi] * g_U2[(size_t)pos * 128 + e * LR + r];
        if (r == 0) sEl[tok][k] = e;
    }
    __syncthreads();

#pragma unroll 4
    for (int it = 0; it < 32; it++) {
        int idx = tid + it * 256;
        int tok = idx >> 7, col = idx & 127;
        float d = 0.f;
#pragma unroll
        for (int k = 0; k < 2; k++) {
            const float* a2c = &sA2[sEl[tok][k] * 2048 + col];
            const float* u = &sU[tok][k * 16];
#pragma unroll
            for (int r = 0; r < LR; r++) d += u[r] * a2c[r * 128];
        }
        size_t oidx = (size_t)(t0 + tok) * D + col0 + col;
        out[oidx] += ALPHA * d;
    }
}

// ---------------- launch ----------------------------------------------------
extern "C" void kernel_launch(void* const* d_in, const int* in_sizes, int n_in,
                              void* d_out, int out_size)
{
    const float* X     = (const float*)d_in[0];
    const float* Wg    = (const float*)d_in[1];
    const float* Wup   = (const float*)d_in[2];
    const float* Wgate = (const float*)d_in[3];
    const float* Wdown = (const float*)d_in[4];
    const float* A1    = (const float*)d_in[5];
    const float* B1    = (const float*)d_in[6];
    const float* A2    = (const float*)d_in[7];
    const float* B2    = (const float*)d_in[8];
    const float* A3    = (const float*)d_in[9];
    const float* B3    = (const float*)d_in[10];
    float* out = (float*)d_out;

    static __half *pXh = nullptr, *pW13B, *pWdh, *pB2h, *pHph, *pHc, *pH13h;
    static float  *pU2;
    if (!pXh) {
        cudaGetSymbolAddress((void**)&pXh,   g_Xh);
        cudaGetSymbolAddress((void**)&pW13B, g_W13B);
        cudaGetSymbolAddress((void**)&pWdh,  g_Wdh);
        cudaGetSymbolAddress((void**)&pB2h,  g_B2h);
        cudaGetSymbolAddress((void**)&pHph,  g_Hph);
        cudaGetSymbolAddress((void**)&pHc,   g_Hc);
        cudaGetSymbolAddress((void**)&pH13h, g_H13h);
        cudaGetSymbolAddress((void**)&pU2,   g_U2);
        cudaFuncSetAttribute(gemm_h16<__half>,
            cudaFuncAttributeMaxDynamicSharedMemorySize, 3 * STAGE_BY);
        cudaFuncSetAttribute(gemm_h16<float>,
            cudaFuncAttributeMaxDynamicSharedMemorySize, 3 * STAGE_BY);
        cudaFuncSetAttribute(final_delta_kernel,
            cudaFuncAttributeMaxDynamicSharedMemorySize, 65536);
    }
    const int SMB = 3 * STAGE_BY;   // 98304

    auto cvt = [&](const float* s, __half* d, size_t n) {
        int n4 = (int)(n / 4);
        to_half_kernel<<<(n4 + 1023) / 1024, 256>>>((const float4*)s, (__half2*)d, n4);
    };

    // Launches 1-5: converts feeding GEMM1; launch 6 = GEMM1 (ncu slot)
    cvt(X,     pXh,                      (size_t)TT * D);
    cvt(Wup,   pW13B,                    (size_t)D * D);
    cvt(Wgate, pW13B + (size_t)D * D,    (size_t)D * D);
    cvt(B1,    pW13B + (size_t)2 * D * D,(size_t)128 * D);
    cvt(B3,    pW13B + (size_t)2 * D * D + (size_t)128 * D, (size_t)128 * D);

    // H13h = Xh @ [Wup;Wgate;B1;B3]^T    [8192 x 4352] fp16
    gemm_h16<__half><<<dim3(N13 / 128, TT / 128), 256, SMB>>>(pXh, pW13B, pH13h, N13, D);

    cvt(Wdown, pWdh,                     (size_t)D * D);
    cvt(B2,    pB2h,                     (size_t)128 * D);

    reset_kernel<<<(MP + 255) / 256, 256>>>();
    router_kernel<<<TT * 32 / 256, 256>>>(X, Wg);
    scan_kernel<<<1, 1>>>();
    assign_kernel<<<(TT * 2 + 255) / 256, 256>>>();

    pair_up_kernel<<<dim3(MP / 32, D / 128), 256>>>(A1, A3);

    combine_kernel<<<TT * (D / 8) / 256, 256>>>();

    // U2 = Hph @ B2^T                    [16640 x 128]
    gemm_h16<float><<<dim3(1, MP / 128), 256, SMB>>>(pHph, pB2h, pU2, 128, D);

    // out_base = Hc @ Wdown^T            [8192 x 2048]  (writes d_out directly)
    gemm_h16<float><<<dim3(D / 128, TT / 128), 256, SMB>>>(pHc, pWdh, out, D, D);

    final_delta_kernel<<<dim3(D / 128, TT / 64), 256, 65536>>>(A2, out);
    (void)in_sizes; (void)n_in; (void)out_size;
}